// round 2
// baseline (speedup 1.0000x reference)
#include <cuda_runtime.h>
#include <cstdint>

#define S_T     4              // s positions per block
#define B_T     128            // batches per block
#define FT      32             // f elements per chunk
#define NC      24             // 768 / FT chunks
#define NROWS   6              // S_T + 2 input rows
#define XPAD    34             // FT + 2 (bank-conflict-free float2 reads)
#define XC_FLOATS (NROWS * B_T * XPAD)            // 26112
#define WC_FLOATS (S_T * 3 * (FT/2) * 6 * 2)      // 2304
#define SEQ     256
#define FEAT    768
#define NFILT   6
#define SMEM_BYTES ((2*XC_FLOATS + 2*WC_FLOATS) * 4)   // 227328

__device__ __forceinline__ uint32_t s2u(const void* p) {
    uint32_t a;
    asm("{ .reg .u64 t; cvta.to.shared.u64 t, %1; cvt.u32.u64 %0, t; }"
        : "=r"(a) : "l"(p));
    return a;
}
__device__ __forceinline__ void cp8(uint32_t dst, const void* src, uint32_t sz) {
    asm volatile("cp.async.ca.shared.global [%0], [%1], 8, %2;"
                 :: "r"(dst), "l"(src), "r"(sz));
}
__device__ __forceinline__ void cp4(uint32_t dst, const void* src) {
    asm volatile("cp.async.ca.shared.global [%0], [%1], 4;"
                 :: "r"(dst), "l"(src));
}
__device__ __forceinline__ void cp_commit() {
    asm volatile("cp.async.commit_group;");
}
template<int N>
__device__ __forceinline__ void cp_wait() {
    asm volatile("cp.async.wait_group %0;" :: "n"(N));
}
// packed fp32x2 FMA: acc.lo += a.lo*b.lo; acc.hi += a.hi*b.hi
__device__ __forceinline__ void ffma2(unsigned long long& acc,
                                      unsigned long long a,
                                      unsigned long long b) {
    asm("fma.rn.f32x2 %0, %1, %2, %0;" : "+l"(acc) : "l"(a), "l"(b));
}

__global__ __launch_bounds__(256, 1)
void poslin_kernel(const float* __restrict__ in,   // [256, 256, 768]
                   const float* __restrict__ Wt,   // [256, 2304, 6]
                   const float* __restrict__ bias, // [256, 6]
                   float* __restrict__ out)        // [256, 256, 6]
{
    extern __shared__ float smem[];
    float* xc = smem;                     // 2 buffers of XC_FLOATS
    float* wc = smem + 2 * XC_FLOATS;     // 2 buffers of WC_FLOATS

    const int tid   = threadIdx.x;
    const int s0    = blockIdx.x * S_T;
    const int b0    = blockIdx.y * B_T;
    const int bl    = tid & 127;          // local batch
    const int khalf = tid >> 7;           // k-pair half (0/1)

    // x-staging decode (constant per thread)
    const int u0  = tid >> 4;             // 0..15
    const int f20 = tid & 15;             // float2 index within FT

    // Precompute W staging offsets: 9 elements per thread cover 2304 floats/chunk
    uint32_t wdst[9], wsrc[9];
    #pragma unroll
    for (int j = 0; j < 9; j++) {
        int i  = tid + 256 * j;           // 0..2303
        int o  = i % 6;
        int j2 = (i / 6) & 1;
        int kp = (i / 12) & 15;
        int w  = (i / 192) % 3;
        int sl = i / 576;
        wdst[j] = (uint32_t)((((sl * 3 + w) * 16 + kp) * 6 + o) * 2 + j2);
        wsrc[j] = ((uint32_t)(s0 + sl) * 2304u + (uint32_t)(w * 768 + 2 * kp + j2)) * 6u
                  + (uint32_t)o;
    }

    const uint32_t xc_u32 = s2u(xc);
    const uint32_t wc_u32 = s2u(wc);

    auto stage = [&](int c, int buf) {
        const int f0 = c * FT;
        // x: 6 rows x 128 b x 32 f, stored transposed xc[row][b][f] (pad 34)
        #pragma unroll
        for (int rl = 0; rl < NROWS; rl++) {
            int r = s0 - 1 + rl;
            uint32_t sz = ((unsigned)r < 256u) ? 8u : 0u;
            int rr = r < 0 ? 0 : (r > 255 ? 255 : r);
            const float* srow = in + ((size_t)(b0 + u0) * SEQ + rr) * FEAT + f0 + 2 * f20;
            uint32_t drow = xc_u32
                + (uint32_t)(buf * XC_FLOATS + (rl * B_T + u0) * XPAD + 2 * f20) * 4u;
            #pragma unroll
            for (int jb = 0; jb < 8; jb++) {
                cp8(drow + (uint32_t)(16 * jb * XPAD) * 4u,
                    srow + (size_t)16 * jb * SEQ * FEAT, sz);
            }
        }
        // W: pre-paired float2 (k, k+1) per (sl, w, kp, o)
        const float* wchunk = Wt + (size_t)f0 * 6;
        uint32_t wbase = wc_u32 + (uint32_t)(buf * WC_FLOATS) * 4u;
        #pragma unroll
        for (int j = 0; j < 9; j++) {
            cp4(wbase + wdst[j] * 4u, wchunk + wsrc[j]);
        }
        cp_commit();
    };

    unsigned long long acc[S_T][NFILT];
    #pragma unroll
    for (int sl = 0; sl < S_T; sl++)
        #pragma unroll
        for (int o = 0; o < NFILT; o++)
            acc[sl][o] = 0ULL;

    auto compute = [&](int buf) {
        const float* xb = xc + buf * XC_FLOATS;
        const ulonglong2* wb = (const ulonglong2*)(wc + buf * WC_FLOATS);
        #pragma unroll
        for (int sl = 0; sl < S_T; sl++) {
            #pragma unroll
            for (int w = 0; w < 3; w++) {
                const unsigned long long* xrow =
                    (const unsigned long long*)(xb + ((sl + w) * B_T + bl) * XPAD);
                const ulonglong2* wrow = wb + (sl * 3 + w) * 16 * 3;
                #pragma unroll
                for (int kk = 0; kk < 8; kk++) {
                    int kp = khalf * 8 + kk;
                    unsigned long long x2 = xrow[kp];
                    ulonglong2 wa = wrow[kp * 3 + 0];
                    ulonglong2 wv = wrow[kp * 3 + 1];
                    ulonglong2 wz = wrow[kp * 3 + 2];
                    ffma2(acc[sl][0], x2, wa.x);
                    ffma2(acc[sl][1], x2, wa.y);
                    ffma2(acc[sl][2], x2, wv.x);
                    ffma2(acc[sl][3], x2, wv.y);
                    ffma2(acc[sl][4], x2, wz.x);
                    ffma2(acc[sl][5], x2, wz.y);
                }
            }
        }
    };

    stage(0, 0);
    #pragma unroll 1
    for (int c = 0; c < NC; c++) {
        int buf = c & 1;
        if (c + 1 < NC) {
            stage(c + 1, buf ^ 1);
            cp_wait<1>();
        } else {
            cp_wait<0>();
        }
        __syncthreads();
        compute(buf);
        __syncthreads();
    }

    // Collapse f32x2 halves
    float v[S_T * NFILT];
    #pragma unroll
    for (int sl = 0; sl < S_T; sl++) {
        #pragma unroll
        for (int o = 0; o < NFILT; o++) {
            union { unsigned long long u; float2 f; } cv;
            cv.u = acc[sl][o];
            v[sl * NFILT + o] = cv.f.x + cv.f.y;
        }
    }

    // Cross-khalf reduction through (reused) smem
    float* red = smem;  // 128 * 24 floats, fits in retired xc buffer
    if (khalf == 1) {
        #pragma unroll
        for (int i = 0; i < S_T * NFILT; i++)
            red[bl * (S_T * NFILT) + i] = v[i];
    }
    __syncthreads();
    if (khalf == 0) {
        const int b = b0 + bl;
        float res[S_T * NFILT];
        #pragma unroll
        for (int sl = 0; sl < S_T; sl++) {
            #pragma unroll
            for (int o = 0; o < NFILT; o++) {
                int i = sl * NFILT + o;
                float r = v[i] + red[bl * (S_T * NFILT) + i]
                        + __ldg(bias + (s0 + sl) * NFILT + o);
                res[i] = fmaxf(r, 0.0f);
            }
        }
        // 24 contiguous floats: out[b][s0..s0+3][0..5] -> 6 float4 stores
        float4* op = (float4*)(out + (size_t)b * (SEQ * NFILT) + s0 * NFILT);
        #pragma unroll
        for (int q = 0; q < 6; q++) {
            op[q] = make_float4(res[4 * q + 0], res[4 * q + 1],
                                res[4 * q + 2], res[4 * q + 3]);
        }
    }
}

extern "C" void kernel_launch(void* const* d_in, const int* in_sizes, int n_in,
                              void* d_out, int out_size)
{
    const float* in   = (const float*)d_in[0];
    const float* Wt   = (const float*)d_in[1];
    const float* bias = (const float*)d_in[2];
    float* out = (float*)d_out;

    cudaFuncSetAttribute(poslin_kernel,
                         cudaFuncAttributeMaxDynamicSharedMemorySize, SMEM_BYTES);
    dim3 grid(SEQ / S_T, 256 / B_T);   // (64, 2) = 128 blocks
    poslin_kernel<<<grid, 256, SMEM_BYTES>>>(in, Wt, bias, out);
}

// round 3
// speedup vs baseline: 1.0002x; 1.0002x over previous
#include <cuda_runtime.h>
#include <cstdint>

#define S_T     4              // s positions per block
#define B_T     128            // batches per block
#define FT      32             // f elements per chunk
#define NC      24             // 768 / FT chunks
#define NROWS   6              // S_T + 2 input rows
#define XPAD    34             // FT + 2 (bank-conflict-free float2 reads)
#define XC_FLOATS (NROWS * B_T * XPAD)            // 26112
#define WC_FLOATS (S_T * 3 * (FT/2) * 6 * 2)      // 2304
#define SEQ     256
#define FEAT    768
#define NFILT   6
#define SMEM_BYTES ((2*XC_FLOATS + 2*WC_FLOATS) * 4)   // 227328

__device__ __forceinline__ uint32_t s2u(const void* p) {
    uint32_t a;
    asm("{ .reg .u64 t; cvta.to.shared.u64 t, %1; cvt.u32.u64 %0, t; }"
        : "=r"(a) : "l"(p));
    return a;
}
__device__ __forceinline__ void cp8(uint32_t dst, const void* src, uint32_t sz) {
    asm volatile("cp.async.ca.shared.global [%0], [%1], 8, %2;"
                 :: "r"(dst), "l"(src), "r"(sz));
}
__device__ __forceinline__ void cp4(uint32_t dst, const void* src) {
    asm volatile("cp.async.ca.shared.global [%0], [%1], 4;"
                 :: "r"(dst), "l"(src));
}
__device__ __forceinline__ void cp_commit() {
    asm volatile("cp.async.commit_group;");
}
template<int N>
__device__ __forceinline__ void cp_wait() {
    asm volatile("cp.async.wait_group %0;" :: "n"(N));
}
// packed fp32x2 FMA: acc.lo += a.lo*b.lo; acc.hi += a.hi*b.hi
__device__ __forceinline__ void ffma2(unsigned long long& acc,
                                      unsigned long long a,
                                      unsigned long long b) {
    asm("fma.rn.f32x2 %0, %1, %2, %0;" : "+l"(acc) : "l"(a), "l"(b));
}

__global__ __launch_bounds__(256, 1)
void poslin_kernel(const float* __restrict__ in,   // [256, 256, 768]
                   const float* __restrict__ Wt,   // [256, 2304, 6]
                   const float* __restrict__ bias, // [256, 6]
                   float* __restrict__ out)        // [256, 256, 6]
{
    extern __shared__ float smem[];
    float* xc = smem;                     // 2 buffers of XC_FLOATS
    float* wc = smem + 2 * XC_FLOATS;     // 2 buffers of WC_FLOATS

    const int tid   = threadIdx.x;
    const int s0    = blockIdx.x * S_T;
    const int b0    = blockIdx.y * B_T;
    const int bl    = tid & 127;          // local batch
    const int khalf = tid >> 7;           // k-pair half (0/1)

    // x-staging decode (constant per thread)
    const int u0  = tid >> 4;             // 0..15
    const int f20 = tid & 15;             // float2 index within FT

    // Precompute W staging offsets: 9 elements per thread cover 2304 floats/chunk
    uint32_t wdst[9], wsrc[9];
    #pragma unroll
    for (int j = 0; j < 9; j++) {
        int i  = tid + 256 * j;           // 0..2303
        int o  = i % 6;
        int j2 = (i / 6) & 1;
        int kp = (i / 12) & 15;
        int w  = (i / 192) % 3;
        int sl = i / 576;
        wdst[j] = (uint32_t)((((sl * 3 + w) * 16 + kp) * 6 + o) * 2 + j2);
        wsrc[j] = ((uint32_t)(s0 + sl) * 2304u + (uint32_t)(w * 768 + 2 * kp + j2)) * 6u
                  + (uint32_t)o;
    }

    const uint32_t xc_u32 = s2u(xc);
    const uint32_t wc_u32 = s2u(wc);

    auto stage = [&](int c, int buf) {
        const int f0 = c * FT;
        // x: 6 rows x 128 b x 32 f, stored transposed xc[row][b][f] (pad 34)
        #pragma unroll
        for (int rl = 0; rl < NROWS; rl++) {
            int r = s0 - 1 + rl;
            uint32_t sz = ((unsigned)r < 256u) ? 8u : 0u;
            int rr = r < 0 ? 0 : (r > 255 ? 255 : r);
            const float* srow = in + ((size_t)(b0 + u0) * SEQ + rr) * FEAT + f0 + 2 * f20;
            uint32_t drow = xc_u32
                + (uint32_t)(buf * XC_FLOATS + (rl * B_T + u0) * XPAD + 2 * f20) * 4u;
            #pragma unroll
            for (int jb = 0; jb < 8; jb++) {
                cp8(drow + (uint32_t)(16 * jb * XPAD) * 4u,
                    srow + (size_t)16 * jb * SEQ * FEAT, sz);
            }
        }
        // W: pre-paired float2 (k, k+1) per (sl, w, kp, o)
        const float* wchunk = Wt + (size_t)f0 * 6;
        uint32_t wbase = wc_u32 + (uint32_t)(buf * WC_FLOATS) * 4u;
        #pragma unroll
        for (int j = 0; j < 9; j++) {
            cp4(wbase + wdst[j] * 4u, wchunk + wsrc[j]);
        }
        cp_commit();
    };

    unsigned long long acc[S_T][NFILT];
    #pragma unroll
    for (int sl = 0; sl < S_T; sl++)
        #pragma unroll
        for (int o = 0; o < NFILT; o++)
            acc[sl][o] = 0ULL;

    auto compute = [&](int buf) {
        const float* xb = xc + buf * XC_FLOATS;
        const ulonglong2* wb = (const ulonglong2*)(wc + buf * WC_FLOATS);
        #pragma unroll
        for (int sl = 0; sl < S_T; sl++) {
            #pragma unroll
            for (int w = 0; w < 3; w++) {
                const unsigned long long* xrow =
                    (const unsigned long long*)(xb + ((sl + w) * B_T + bl) * XPAD);
                const ulonglong2* wrow = wb + (sl * 3 + w) * 16 * 3;
                #pragma unroll
                for (int kk = 0; kk < 8; kk++) {
                    int kp = khalf * 8 + kk;
                    unsigned long long x2 = xrow[kp];
                    ulonglong2 wa = wrow[kp * 3 + 0];
                    ulonglong2 wv = wrow[kp * 3 + 1];
                    ulonglong2 wz = wrow[kp * 3 + 2];
                    ffma2(acc[sl][0], x2, wa.x);
                    ffma2(acc[sl][1], x2, wa.y);
                    ffma2(acc[sl][2], x2, wv.x);
                    ffma2(acc[sl][3], x2, wv.y);
                    ffma2(acc[sl][4], x2, wz.x);
                    ffma2(acc[sl][5], x2, wz.y);
                }
            }
        }
    };

    stage(0, 0);
    #pragma unroll 1
    for (int c = 0; c < NC; c++) {
        int buf = c & 1;
        if (c + 1 < NC) {
            stage(c + 1, buf ^ 1);
            cp_wait<1>();
        } else {
            cp_wait<0>();
        }
        __syncthreads();
        compute(buf);
        __syncthreads();
    }

    // Collapse f32x2 halves
    float v[S_T * NFILT];
    #pragma unroll
    for (int sl = 0; sl < S_T; sl++) {
        #pragma unroll
        for (int o = 0; o < NFILT; o++) {
            union { unsigned long long u; float2 f; } cv;
            cv.u = acc[sl][o];
            v[sl * NFILT + o] = cv.f.x + cv.f.y;
        }
    }

    // Cross-khalf reduction through (reused) smem
    float* red = smem;  // 128 * 24 floats, fits in retired xc buffer
    if (khalf == 1) {
        #pragma unroll
        for (int i = 0; i < S_T * NFILT; i++)
            red[bl * (S_T * NFILT) + i] = v[i];
    }
    __syncthreads();
    if (khalf == 0) {
        const int b = b0 + bl;
        float res[S_T * NFILT];
        #pragma unroll
        for (int sl = 0; sl < S_T; sl++) {
            #pragma unroll
            for (int o = 0; o < NFILT; o++) {
                int i = sl * NFILT + o;
                float r = v[i] + red[bl * (S_T * NFILT) + i]
                        + __ldg(bias + (s0 + sl) * NFILT + o);
                res[i] = fmaxf(r, 0.0f);
            }
        }
        // 24 contiguous floats: out[b][s0..s0+3][0..5] -> 6 float4 stores
        float4* op = (float4*)(out + (size_t)b * (SEQ * NFILT) + s0 * NFILT);
        #pragma unroll
        for (int q = 0; q < 6; q++) {
            op[q] = make_float4(res[4 * q + 0], res[4 * q + 1],
                                res[4 * q + 2], res[4 * q + 3]);
        }
    }
}

extern "C" void kernel_launch(void* const* d_in, const int* in_sizes, int n_in,
                              void* d_out, int out_size)
{
    const float* in   = (const float*)d_in[0];
    const float* Wt   = (const float*)d_in[1];
    const float* bias = (const float*)d_in[2];
    float* out = (float*)d_out;

    cudaFuncSetAttribute(poslin_kernel,
                         cudaFuncAttributeMaxDynamicSharedMemorySize, SMEM_BYTES);
    dim3 grid(SEQ / S_T, 256 / B_T);   // (64, 2) = 128 blocks
    poslin_kernel<<<grid, 256, SMEM_BYTES>>>(in, Wt, bias, out);
}

// round 4
// speedup vs baseline: 1.0024x; 1.0022x over previous
#include <cuda_runtime.h>
#include <cstdint>

#define S_T     4              // s positions per block
#define B_T     128            // batches per block
#define FT      32             // f elements per chunk
#define NC      24             // 768 / FT chunks
#define NROWS   6              // S_T + 2 input rows
#define XPAD    34             // FT + 2 (bank-conflict-free float2 reads)
#define XC_FLOATS (NROWS * B_T * XPAD)            // 26112
#define WC_FLOATS (S_T * 3 * (FT/2) * 6 * 2)      // 2304
#define SEQ     256
#define FEAT    768
#define NFILT   6
#define SMEM_BYTES ((2*XC_FLOATS + 2*WC_FLOATS) * 4)   // 227328

__device__ __forceinline__ uint32_t s2u(const void* p) {
    uint32_t a;
    asm("{ .reg .u64 t; cvta.to.shared.u64 t, %1; cvt.u32.u64 %0, t; }"
        : "=r"(a) : "l"(p));
    return a;
}
__device__ __forceinline__ void cp8(uint32_t dst, const void* src, uint32_t sz) {
    asm volatile("cp.async.ca.shared.global [%0], [%1], 8, %2;"
                 :: "r"(dst), "l"(src), "r"(sz));
}
__device__ __forceinline__ void cp4(uint32_t dst, const void* src) {
    asm volatile("cp.async.ca.shared.global [%0], [%1], 4;"
                 :: "r"(dst), "l"(src));
}
__device__ __forceinline__ void cp_commit() {
    asm volatile("cp.async.commit_group;");
}
template<int N>
__device__ __forceinline__ void cp_wait() {
    asm volatile("cp.async.wait_group %0;" :: "n"(N));
}
// packed fp32x2 FMA: acc.lo += a.lo*b.lo; acc.hi += a.hi*b.hi
__device__ __forceinline__ void ffma2(unsigned long long& acc,
                                      unsigned long long a,
                                      unsigned long long b) {
    asm("fma.rn.f32x2 %0, %1, %2, %0;" : "+l"(acc) : "l"(a), "l"(b));
}

__global__ __launch_bounds__(256, 1)
void poslin_kernel(const float* __restrict__ in,   // [256, 256, 768]
                   const float* __restrict__ Wt,   // [256, 2304, 6]
                   const float* __restrict__ bias, // [256, 6]
                   float* __restrict__ out)        // [256, 256, 6]
{
    extern __shared__ float smem[];
    float* xc = smem;                     // 2 buffers of XC_FLOATS
    float* wc = smem + 2 * XC_FLOATS;     // 2 buffers of WC_FLOATS

    const int tid   = threadIdx.x;
    const int s0    = blockIdx.x * S_T;
    const int b0    = blockIdx.y * B_T;
    const int bl    = tid & 127;          // local batch
    const int khalf = tid >> 7;           // k-pair half (0/1)

    // x-staging decode (constant per thread)
    const int u0  = tid >> 4;             // 0..15
    const int f20 = tid & 15;             // float2 index within FT

    // Precompute W staging offsets: 9 elements per thread cover 2304 floats/chunk
    uint32_t wdst[9], wsrc[9];
    #pragma unroll
    for (int j = 0; j < 9; j++) {
        int i  = tid + 256 * j;           // 0..2303
        int o  = i % 6;
        int j2 = (i / 6) & 1;
        int kp = (i / 12) & 15;
        int w  = (i / 192) % 3;
        int sl = i / 576;
        wdst[j] = (uint32_t)((((sl * 3 + w) * 16 + kp) * 6 + o) * 2 + j2);
        wsrc[j] = ((uint32_t)(s0 + sl) * 2304u + (uint32_t)(w * 768 + 2 * kp + j2)) * 6u
                  + (uint32_t)o;
    }

    const uint32_t xc_u32 = s2u(xc);
    const uint32_t wc_u32 = s2u(wc);

    auto stage = [&](int c, int buf) {
        const int f0 = c * FT;
        // x: 6 rows x 128 b x 32 f, stored transposed xc[row][b][f] (pad 34)
        #pragma unroll
        for (int rl = 0; rl < NROWS; rl++) {
            int r = s0 - 1 + rl;
            uint32_t sz = ((unsigned)r < 256u) ? 8u : 0u;
            int rr = r < 0 ? 0 : (r > 255 ? 255 : r);
            const float* srow = in + ((size_t)(b0 + u0) * SEQ + rr) * FEAT + f0 + 2 * f20;
            uint32_t drow = xc_u32
                + (uint32_t)(buf * XC_FLOATS + (rl * B_T + u0) * XPAD + 2 * f20) * 4u;
            #pragma unroll
            for (int jb = 0; jb < 8; jb++) {
                cp8(drow + (uint32_t)(16 * jb * XPAD) * 4u,
                    srow + (size_t)16 * jb * SEQ * FEAT, sz);
            }
        }
        // W: pre-paired float2 (k, k+1) per (sl, w, kp, o)
        const float* wchunk = Wt + (size_t)f0 * 6;
        uint32_t wbase = wc_u32 + (uint32_t)(buf * WC_FLOATS) * 4u;
        #pragma unroll
        for (int j = 0; j < 9; j++) {
            cp4(wbase + wdst[j] * 4u, wchunk + wsrc[j]);
        }
        cp_commit();
    };

    unsigned long long acc[S_T][NFILT];
    #pragma unroll
    for (int sl = 0; sl < S_T; sl++)
        #pragma unroll
        for (int o = 0; o < NFILT; o++)
            acc[sl][o] = 0ULL;

    auto compute = [&](int buf) {
        const float* xb = xc + buf * XC_FLOATS;
        const ulonglong2* wb = (const ulonglong2*)(wc + buf * WC_FLOATS);
        #pragma unroll
        for (int sl = 0; sl < S_T; sl++) {
            #pragma unroll
            for (int w = 0; w < 3; w++) {
                const unsigned long long* xrow =
                    (const unsigned long long*)(xb + ((sl + w) * B_T + bl) * XPAD);
                const ulonglong2* wrow = wb + (sl * 3 + w) * 16 * 3;
                #pragma unroll
                for (int kk = 0; kk < 8; kk++) {
                    int kp = khalf * 8 + kk;
                    unsigned long long x2 = xrow[kp];
                    ulonglong2 wa = wrow[kp * 3 + 0];
                    ulonglong2 wv = wrow[kp * 3 + 1];
                    ulonglong2 wz = wrow[kp * 3 + 2];
                    ffma2(acc[sl][0], x2, wa.x);
                    ffma2(acc[sl][1], x2, wa.y);
                    ffma2(acc[sl][2], x2, wv.x);
                    ffma2(acc[sl][3], x2, wv.y);
                    ffma2(acc[sl][4], x2, wz.x);
                    ffma2(acc[sl][5], x2, wz.y);
                }
            }
        }
    };

    stage(0, 0);
    #pragma unroll 1
    for (int c = 0; c < NC; c++) {
        int buf = c & 1;
        if (c + 1 < NC) {
            stage(c + 1, buf ^ 1);
            cp_wait<1>();
        } else {
            cp_wait<0>();
        }
        __syncthreads();
        compute(buf);
        __syncthreads();
    }

    // Collapse f32x2 halves
    float v[S_T * NFILT];
    #pragma unroll
    for (int sl = 0; sl < S_T; sl++) {
        #pragma unroll
        for (int o = 0; o < NFILT; o++) {
            union { unsigned long long u; float2 f; } cv;
            cv.u = acc[sl][o];
            v[sl * NFILT + o] = cv.f.x + cv.f.y;
        }
    }

    // Cross-khalf reduction through (reused) smem
    float* red = smem;  // 128 * 24 floats, fits in retired xc buffer
    if (khalf == 1) {
        #pragma unroll
        for (int i = 0; i < S_T * NFILT; i++)
            red[bl * (S_T * NFILT) + i] = v[i];
    }
    __syncthreads();
    if (khalf == 0) {
        const int b = b0 + bl;
        float res[S_T * NFILT];
        #pragma unroll
        for (int sl = 0; sl < S_T; sl++) {
            #pragma unroll
            for (int o = 0; o < NFILT; o++) {
                int i = sl * NFILT + o;
                float r = v[i] + red[bl * (S_T * NFILT) + i]
                        + __ldg(bias + (s0 + sl) * NFILT + o);
                res[i] = fmaxf(r, 0.0f);
            }
        }
        // 24 contiguous floats: out[b][s0..s0+3][0..5] -> 6 float4 stores
        float4* op = (float4*)(out + (size_t)b * (SEQ * NFILT) + s0 * NFILT);
        #pragma unroll
        for (int q = 0; q < 6; q++) {
            op[q] = make_float4(res[4 * q + 0], res[4 * q + 1],
                                res[4 * q + 2], res[4 * q + 3]);
        }
    }
}

extern "C" void kernel_launch(void* const* d_in, const int* in_sizes, int n_in,
                              void* d_out, int out_size)
{
    const float* in   = (const float*)d_in[0];
    const float* Wt   = (const float*)d_in[1];
    const float* bias = (const float*)d_in[2];
    float* out = (float*)d_out;

    cudaFuncSetAttribute(poslin_kernel,
                         cudaFuncAttributeMaxDynamicSharedMemorySize, SMEM_BYTES);
    dim3 grid(SEQ / S_T, 256 / B_T);   // (64, 2) = 128 blocks
    poslin_kernel<<<grid, 256, SMEM_BYTES>>>(in, Wt, bias, out);
}